// round 15
// baseline (speedup 1.0000x reference)
#include <cuda_runtime.h>
#include <cuda_fp16.h>
#include <math.h>
#include <stdint.h>

#define B 32
#define DIN 2048
#define D 128
#define NREPS 400000
#define ADIM 7
#define KSEL 5
#define NCAND 40                  /* 8 warps x depth-5 lists -> exact rescore */

#define GRID_MAIN 296
#define TILE_N 128
#define NTILES (NREPS / TILE_N)   /* 3125, exact */
#define ENC_CHUNKS 16

/* smem layout (bytes) */
#define ABUF(buf)   ((buf) * 32768)   /* 1 f16 plane: 128 rows x 256B, XOR-swizzled */
#define BT_OFF      65536             /* B frag table: [kk*4+nb][lane*8] = 8192 B */
#define NPART_OFF   73728             /* [buf][128] floats = 1024 B */
#define SMEM_TOTAL  74752

/* ---------------- device scratch ---------------- */
__device__ float g_enc_part[ENC_CHUNKS][B][D];
__device__ float g_batch[B * D];
__device__ float g_anorm[B];
__device__ float g_ckey[B * GRID_MAIN * KSEL];
__device__ int   g_cidx[B * GRID_MAIN * KSEL];

/* ---------------- helpers ---------------- */
__device__ __forceinline__ unsigned cvtf16x2(float hi, float lo) {  /* d.hi=cvt(hi), d.lo=cvt(lo) */
    unsigned r;
    asm("cvt.rn.f16x2.f32 %0, %1, %2;" : "=r"(r) : "f"(hi), "f"(lo));
    return r;
}
__device__ __forceinline__ void mma16816f16(unsigned* c, uint4 a, uint2 b) {
    asm volatile(
        "mma.sync.aligned.m16n8k16.row.col.f16.f16.f16.f16 "
        "{%0,%1}, {%2,%3,%4,%5}, {%6,%7}, {%0,%1};"
        : "+r"(c[0]), "+r"(c[1])
        : "r"(a.x), "r"(a.y), "r"(a.z), "r"(a.w), "r"(b.x), "r"(b.y));
}
__device__ __forceinline__ uint4 ldsm_x4(unsigned addr) {
    uint4 r;
    asm volatile("ldmatrix.sync.aligned.m8n8.x4.shared.b16 {%0,%1,%2,%3}, [%4];"
                 : "=r"(r.x), "=r"(r.y), "=r"(r.z), "=r"(r.w) : "r"(addr));
    return r;
}
__device__ __forceinline__ unsigned smem_u32(const void* p) {
    unsigned a;
    asm("{ .reg .u64 t; cvta.to.shared.u64 t, %1; cvt.u32.u64 %0, t; }" : "=r"(a) : "l"(p));
    return a;
}

/* ================= encoder split-K partial ================= */
__global__ void enc_partial(const float* __restrict__ x,
                            const float* __restrict__ W) {
    __shared__ float xs[128];
    int b = blockIdx.x, c = blockIdx.y, t = threadIdx.x;
    xs[t] = x[b * DIN + c * 128 + t];
    __syncthreads();
    const float* Wp = W + (c * 128) * D + t;
    float a0 = 0.f, a1 = 0.f, a2 = 0.f, a3 = 0.f;
#pragma unroll
    for (int k = 0; k < 128; k += 4) {
        a0 = fmaf(xs[k + 0], Wp[(k + 0) * D], a0);
        a1 = fmaf(xs[k + 1], Wp[(k + 1) * D], a1);
        a2 = fmaf(xs[k + 2], Wp[(k + 2) * D], a2);
        a3 = fmaf(xs[k + 3], Wp[(k + 3) * D], a3);
    }
    g_enc_part[c][b][t] = (a0 + a1) + (a2 + a3);
}

/* ================= encoder reduce + norms ================= */
__global__ void enc_reduce(const float* __restrict__ bias) {
    __shared__ float red[4];
    int b = blockIdx.x, t = threadIdx.x;
    float s = bias[t];
#pragma unroll
    for (int c = 0; c < ENC_CHUNKS; c++) s += g_enc_part[c][b][t];
    g_batch[b * D + t] = s;
    float sq = s * s;
#pragma unroll
    for (int o = 16; o > 0; o >>= 1) sq += __shfl_down_sync(0xffffffffu, sq, o);
    if ((t & 31) == 0) red[t >> 5] = sq;
    __syncthreads();
    if (t == 0) g_anorm[b] = red[0] + red[1] + red[2] + red[3];
}

/* ---- convert one tile: warp wid handles rows wid*16..+15 (structure verified R12/R14) ---- */
__device__ __forceinline__ void convert_tile(const float* __restrict__ reps, int rowbase,
                                             char* smem, int buf, int wid, int lane,
                                             float* npart) {
#pragma unroll
    for (int i = 0; i < 16; i++) {
        int r = wid * 16 + i;
        float4 v = ((const float4*)(reps + (size_t)(rowbase + r) * D))[lane];
        unsigned w0 = cvtf16x2(v.y, v.x);
        unsigned w1 = cvtf16x2(v.w, v.z);
        float na = fmaf(v.x, v.x, fmaf(v.y, v.y, fmaf(v.z, v.z, v.w * v.w)));
#pragma unroll
        for (int o = 16; o > 0; o >>= 1) na += __shfl_xor_sync(0xffffffffu, na, o);
        if (lane == 0) npart[buf * 128 + r] = na;
        unsigned off = (unsigned)ABUF(buf) + (unsigned)r * 256u
                     + ((((unsigned)(lane >> 1)) ^ ((unsigned)(r & 7))) << 4)
                     + ((unsigned)(lane & 1)) * 8u;
        *(uint2*)(smem + off) = make_uint2(w0, w1);
    }
}

/* ================= main distance kernel: 1-term f16 mma.sync, f16 accum ================= */
__global__ void __launch_bounds__(256, 2) dist_kernel(const float* __restrict__ reps) {
    extern __shared__ char smem[];
    float* npart = (float*)(smem + NPART_OFF);
    unsigned sb = smem_u32(smem);

    int t = threadIdx.x, wid = t >> 5, lane = t & 31;
    int g = lane >> 2;
    int bid = blockIdx.x;

    /* B fragment table (layout verified R9/R11/R12) */
    for (int e = t; e < 1024; e += 256) {
        int le = e & 31, nb = (e >> 5) & 3, kk = e >> 7;
        int ge = le >> 2, te = le & 3;
        int bcol = 8 * nb + ge;
        int k0 = 16 * kk + 2 * te;
        float v0 = g_batch[bcol * D + k0];
        float v1 = g_batch[bcol * D + k0 + 1];
        float v2 = g_batch[bcol * D + k0 + 8];
        float v3 = g_batch[bcol * D + k0 + 9];
        uint2 w2;
        w2.x = cvtf16x2(v1, v0);
        w2.y = cvtf16x2(v3, v2);
        *(uint2*)(smem + BT_OFF + (size_t)(kk * 4 + nb) * 256 + le * 8) = w2;
    }

    convert_tile(reps, bid * TILE_N, smem, 0, wid, lane, npart);
    __syncthreads();

    unsigned lrow = (unsigned)(lane & 15);
    unsigned lhi  = (unsigned)(lane >> 4);
    unsigned lsw  = (unsigned)(lane & 7);
    unsigned arow = ((unsigned)(wid * 16) + lrow) * 256u;

    float tk[8][4]; int tn[8][4];
#pragma unroll
    for (int li = 0; li < 8; li++)
#pragma unroll
        for (int j = 0; j < 4; j++) { tk[li][j] = 3.0e38f; tn[li][j] = 0; }

    int cur = 0;
    for (int tile = bid; tile < NTILES; tile += GRID_MAIN) {
        int tb = tile * TILE_N;

        unsigned acc[4][2];
#pragma unroll
        for (int nb = 0; nb < 4; nb++) { acc[nb][0] = 0u; acc[nb][1] = 0u; }

        unsigned abase = sb + (unsigned)ABUF(cur) + arow;
        const char* btab = smem + BT_OFF + lane * 8;
#pragma unroll
        for (int kk = 0; kk < 8; kk++) {
            unsigned cc = (unsigned)(2 * kk) + lhi;
            uint4 A0 = ldsm_x4(abase + ((cc ^ lsw) << 4));
#pragma unroll
            for (int nb = 0; nb < 4; nb++) {
                uint2 B0 = *(const uint2*)(btab + (size_t)(kk * 4 + nb) * 256);
                mma16816f16(acc[nb], A0, B0);
            }
        }

        /* keys + insert; fragment element map same positions as f32 variant:
           d0={c0,c1} rows g, cols 2qt/2qt+1; d1={c2,c3} rows g+8 */
        float nn0 = npart[cur * 128 + wid * 16 + g];
        float nn1 = npart[cur * 128 + wid * 16 + g + 8];
        int r0 = tb + wid * 16 + g;
#pragma unroll
        for (int nb = 0; nb < 4; nb++) {
            float2 d0 = __half22float2(*(__half2*)&acc[nb][0]);
            float2 d1 = __half22float2(*(__half2*)&acc[nb][1]);
            float dd[2][2] = {{d0.x, d0.y}, {d1.x, d1.y}};
#pragma unroll
            for (int s = 0; s < 2; s++) {
                int li = nb * 2 + s;
                float k0v = nn0 - 2.0f * dd[0][s];
                float k1v = nn1 - 2.0f * dd[1][s];
#pragma unroll
                for (int which = 0; which < 2; which++) {
                    float kv = which ? k1v : k0v;
                    int   iv = which ? (r0 + 8) : r0;
                    if (kv < tk[li][3]) {
                        tk[li][3] = kv; tn[li][3] = iv;
#pragma unroll
                        for (int m = 3; m > 0; m--) {
                            if (tk[li][m] < tk[li][m - 1]) {
                                float fk = tk[li][m]; tk[li][m] = tk[li][m - 1]; tk[li][m - 1] = fk;
                                int ii = tn[li][m]; tn[li][m] = tn[li][m - 1]; tn[li][m - 1] = ii;
                            }
                        }
                    }
                }
            }
        }

        int next = tile + GRID_MAIN;
        if (next < NTILES)
            convert_tile(reps, next * TILE_N, smem, cur ^ 1, wid, lane, npart);
        __syncthreads();
        cur ^= 1;
    }

    float* mk = (float*)smem;
    int*   mi = (int*)(smem + 32768);
#pragma unroll
    for (int li = 0; li < 8; li++)
#pragma unroll
        for (int j = 0; j < 4; j++) {
            mk[(t * 8 + li) * 4 + j] = tk[li][j];
            mi[(t * 8 + li) * 4 + j] = tn[li][j];
        }
    __syncthreads();

    if (t < 32) {
        int b = t;
        int li = (b >> 3) * 2 + (b & 1);
        int qb = (b >> 1) & 3;
        float fk[5]; int fn[5];
#pragma unroll
        for (int j = 0; j < 5; j++) { fk[j] = 3.0e38f; fn[j] = 0; }
        for (int m = 0; m < 64; m++) {
            int tt = qb + 4 * m;
            int base = (tt * 8 + li) * 4;
#pragma unroll
            for (int j = 0; j < 4; j++) {
                float kv = mk[base + j];
                if (kv < fk[4]) {
                    int iv = mi[base + j];
                    fk[4] = kv; fn[4] = iv;
#pragma unroll
                    for (int m2 = 4; m2 > 0; m2--) {
                        if (fk[m2] < fk[m2 - 1]) {
                            float a2 = fk[m2]; fk[m2] = fk[m2 - 1]; fk[m2 - 1] = a2;
                            int i2 = fn[m2]; fn[m2] = fn[m2 - 1]; fn[m2 - 1] = i2;
                        }
                    }
                } else break;
            }
        }
        int basec = (b * GRID_MAIN + bid) * KSEL;
#pragma unroll
        for (int j = 0; j < 5; j++) { g_ckey[basec + j] = fk[j]; g_cidx[basec + j] = fn[j]; }
    }
}

/* ================= final: depth-5 merge -> 40 cands -> exact rescore -> softmax ================= */
__global__ void __launch_bounds__(256) final_kernel(const float* __restrict__ actions,
                                                    const float* __restrict__ reps,
                                                    float* __restrict__ out) {
    __shared__ float wk[NCAND];
    __shared__ int   wi[NCAND];
    __shared__ float exk[NCAND];
    int b = blockIdx.x, t = threadIdx.x;
    int w = t >> 5, lane = t & 31;

    const int total = GRID_MAIN * KSEL;
    const float* ck = g_ckey + b * total;
    const int*   ci = g_cidx + b * total;

    float tk[5]; int tn[5];
#pragma unroll
    for (int j = 0; j < 5; j++) { tk[j] = 3.0e38f; tn[j] = 0; }
    for (int i = t; i < total; i += 256) {
        float key = ck[i];
        if (key < tk[4]) {
            int idx = ci[i];
            tk[4] = key; tn[4] = idx;
#pragma unroll
            for (int j = 4; j > 0; j--) {
                if (tk[j] < tk[j - 1]) {
                    float fk = tk[j]; tk[j] = tk[j - 1]; tk[j - 1] = fk;
                    int ii = tn[j]; tn[j] = tn[j - 1]; tn[j - 1] = ii;
                }
            }
        }
    }

#pragma unroll
    for (int o = 16; o > 0; o >>= 1) {
        float ok[5]; int on[5];
#pragma unroll
        for (int j = 0; j < 5; j++) {
            ok[j] = __shfl_xor_sync(0xffffffffu, tk[j], o);
            on[j] = __shfl_xor_sync(0xffffffffu, tn[j], o);
        }
#pragma unroll
        for (int j = 0; j < 5; j++) {
            float key = ok[j]; int idx = on[j];
            if (key < tk[4]) {
                tk[4] = key; tn[4] = idx;
#pragma unroll
                for (int m = 4; m > 0; m--) {
                    if (tk[m] < tk[m - 1]) {
                        float fk = tk[m]; tk[m] = tk[m - 1]; tk[m - 1] = fk;
                        int ii = tn[m]; tn[m] = tn[m - 1]; tn[m - 1] = ii;
                    }
                }
            }
        }
    }
    if (lane == 0) {
#pragma unroll
        for (int j = 0; j < 5; j++) { wk[w * KSEL + j] = tk[j]; wi[w * KSEL + j] = tn[j]; }
    }
    __syncthreads();

    /* exact fp32 rescore; warp w does candidates w*5..w*5+4 */
    {
        float4 av = ((const float4*)(g_batch + b * D))[lane];
#pragma unroll
        for (int cc = 0; cc < 5; cc++) {
            int c = w * 5 + cc;
            int idx = wi[c];
            float4 rv = ((const float4*)(reps + (size_t)idx * D))[lane];
            float dot = fmaf(av.x, rv.x, fmaf(av.y, rv.y, fmaf(av.z, rv.z, av.w * rv.w)));
            float rn  = fmaf(rv.x, rv.x, fmaf(rv.y, rv.y, fmaf(rv.z, rv.z, rv.w * rv.w)));
#pragma unroll
            for (int o = 16; o > 0; o >>= 1) {
                dot += __shfl_xor_sync(0xffffffffu, dot, o);
                rn  += __shfl_xor_sync(0xffffffffu, rn, o);
            }
            if (lane == 0) exk[c] = rn - 2.0f * dot;
        }
    }
    __syncthreads();

    if (t == 0) {
        float fk[5]; int fn[5];
#pragma unroll
        for (int j = 0; j < 5; j++) { fk[j] = 3.0e38f; fn[j] = 0; }
#pragma unroll
        for (int c = 0; c < NCAND; c++) {
            float kv = exk[c];
            if (kv < fk[4]) {
                int iv = wi[c];
                fk[4] = kv; fn[4] = iv;
#pragma unroll
                for (int m = 4; m > 0; m--) {
                    if (fk[m] < fk[m - 1]) {
                        float a2 = fk[m]; fk[m] = fk[m - 1]; fk[m - 1] = a2;
                        int i2 = fn[m]; fn[m] = fn[m - 1]; fn[m - 1] = i2;
                    }
                }
            }
        }
        float an = g_anorm[b];
        float dloc[KSEL];
        float dmin = 3.0e38f;
#pragma unroll
        for (int j = 0; j < KSEL; j++) {
            dloc[j] = sqrtf(fmaxf(an + fk[j], 1e-12f));
            dmin = fminf(dmin, dloc[j]);
        }
        float wsum = 0.f;
        float pred[ADIM];
#pragma unroll
        for (int a = 0; a < ADIM; a++) pred[a] = 0.f;
#pragma unroll
        for (int j = 0; j < KSEL; j++) {
            float wgt = expf(-(dloc[j] - dmin));
            wsum += wgt;
            const float* arow = actions + (size_t)fn[j] * ADIM;
#pragma unroll
            for (int a = 0; a < ADIM; a++) pred[a] = fmaf(wgt, arow[a], pred[a]);
        }
        float inv = 1.0f / wsum;
#pragma unroll
        for (int a = 0; a < ADIM; a++) out[b * ADIM + a] = pred[a] * inv;
    }
}

/* ================= launch ================= */
extern "C" void kernel_launch(void* const* d_in, const int* in_sizes, int n_in,
                              void* d_out, int out_size) {
    (void)in_sizes; (void)n_in; (void)out_size;
    const float* x       = (const float*)d_in[0];
    const float* W       = (const float*)d_in[1];
    const float* bias    = (const float*)d_in[2];
    const float* reps    = (const float*)d_in[3];
    const float* actions = (const float*)d_in[4];
    float* out = (float*)d_out;

    cudaFuncSetAttribute(dist_kernel, cudaFuncAttributeMaxDynamicSharedMemorySize, SMEM_TOTAL);

    enc_partial<<<dim3(B, ENC_CHUNKS), 128>>>(x, W);
    enc_reduce<<<B, 128>>>(bias);
    dist_kernel<<<GRID_MAIN, 256, SMEM_TOTAL>>>(reps);
    final_kernel<<<B, 256>>>(actions, reps, out);
}

// round 16
// speedup vs baseline: 1.3856x; 1.3856x over previous
#include <cuda_runtime.h>
#include <math.h>
#include <stdint.h>

#define B 32
#define DIN 2048
#define D 128
#define NREPS 400000
#define ADIM 7
#define KSEL 5
#define NCAND 40                  /* 8 warps x depth-5 lists -> exact rescore */

#define GRID_MAIN 296
#define TILE_N 128
#define NTILES (NREPS / TILE_N)   /* 3125, exact */
#define ENC_CHUNKS 16

/* smem layout (bytes) */
#define ABUF(buf)   ((buf) * 16384)   /* fp8 plane: 128 rows x 128B, chunk^((r&7)<<2) swizzle */
#define BT_OFF      32768             /* B frag table: [(kk*4+nb)*32+lane]*8 = 4096 B */
#define NPART_OFF   65536             /* [buf][128] floats = 1024 B (above merge scratch) */
#define SMEM_TOTAL  66560

/* ---------------- device scratch ---------------- */
__device__ float g_enc_part[ENC_CHUNKS][B][D];
__device__ float g_batch[B * D];
__device__ float g_anorm[B];
__device__ float g_ckey[B * GRID_MAIN * KSEL];
__device__ int   g_cidx[B * GRID_MAIN * KSEL];

/* ---------------- helpers ---------------- */
__device__ __forceinline__ unsigned short cvte4m3x2(float hi, float lo) {
    unsigned short r;
    asm("cvt.rn.satfinite.e4m3x2.f32 %0, %1, %2;" : "=h"(r) : "f"(hi), "f"(lo));
    return r;
}
__device__ __forceinline__ void mma16832fp8(float* c, unsigned a0, unsigned a1,
                                            unsigned a2, unsigned a3,
                                            unsigned b0, unsigned b1) {
    asm volatile(
        "mma.sync.aligned.m16n8k32.row.col.f32.e4m3.e4m3.f32 "
        "{%0,%1,%2,%3}, {%4,%5,%6,%7}, {%8,%9}, {%0,%1,%2,%3};"
        : "+f"(c[0]), "+f"(c[1]), "+f"(c[2]), "+f"(c[3])
        : "r"(a0), "r"(a1), "r"(a2), "r"(a3), "r"(b0), "r"(b1));
}
__device__ __forceinline__ unsigned smem_u32(const void* p) {
    unsigned a;
    asm("{ .reg .u64 t; cvta.to.shared.u64 t, %1; cvt.u32.u64 %0, t; }" : "=r"(a) : "l"(p));
    return a;
}

/* ================= encoder split-K partial ================= */
__global__ void enc_partial(const float* __restrict__ x,
                            const float* __restrict__ W) {
    __shared__ float xs[128];
    int b = blockIdx.x, c = blockIdx.y, t = threadIdx.x;
    xs[t] = x[b * DIN + c * 128 + t];
    __syncthreads();
    const float* Wp = W + (c * 128) * D + t;
    float a0 = 0.f, a1 = 0.f, a2 = 0.f, a3 = 0.f;
#pragma unroll
    for (int k = 0; k < 128; k += 4) {
        a0 = fmaf(xs[k + 0], Wp[(k + 0) * D], a0);
        a1 = fmaf(xs[k + 1], Wp[(k + 1) * D], a1);
        a2 = fmaf(xs[k + 2], Wp[(k + 2) * D], a2);
        a3 = fmaf(xs[k + 3], Wp[(k + 3) * D], a3);
    }
    g_enc_part[c][b][t] = (a0 + a1) + (a2 + a3);
}

/* ================= encoder reduce + norms ================= */
__global__ void enc_reduce(const float* __restrict__ bias) {
    __shared__ float red[4];
    int b = blockIdx.x, t = threadIdx.x;
    float s = bias[t];
#pragma unroll
    for (int c = 0; c < ENC_CHUNKS; c++) s += g_enc_part[c][b][t];
    g_batch[b * D + t] = s;
    float sq = s * s;
#pragma unroll
    for (int o = 16; o > 0; o >>= 1) sq += __shfl_down_sync(0xffffffffu, sq, o);
    if ((t & 31) == 0) red[t >> 5] = sq;
    __syncthreads();
    if (t == 0) g_anorm[b] = red[0] + red[1] + red[2] + red[3];
}

/* ---- convert one tile: warp wid rows wid*16..+15; lane = k-chunk (4 dims).
   STS.32 at r*128 + 4*(lane ^ ((r&7)<<2)) — lane permutation, conflict-free. ---- */
__device__ __forceinline__ void convert_tile(const float* __restrict__ reps, int rowbase,
                                             char* smem, int buf, int wid, int lane,
                                             float* npart) {
#pragma unroll
    for (int i = 0; i < 16; i++) {
        int r = wid * 16 + i;
        float4 v = ((const float4*)(reps + (size_t)(rowbase + r) * D))[lane];
        unsigned lo = cvte4m3x2(v.y, v.x);
        unsigned hi = cvte4m3x2(v.w, v.z);
        unsigned word = lo | (hi << 16);
        float na = fmaf(v.x, v.x, fmaf(v.y, v.y, fmaf(v.z, v.z, v.w * v.w)));
#pragma unroll
        for (int o = 16; o > 0; o >>= 1) na += __shfl_xor_sync(0xffffffffu, na, o);
        if (lane == 0) npart[buf * 128 + r] = na;
        unsigned off = (unsigned)ABUF(buf) + (unsigned)r * 128u
                     + (((unsigned)lane ^ (((unsigned)(r & 7)) << 2)) << 2);
        *(unsigned*)(smem + off) = word;
    }
}

/* ================= main distance kernel: fp8 m16n8k32 mma.sync ================= */
__global__ void __launch_bounds__(256, 2) dist_kernel(const float* __restrict__ reps) {
    extern __shared__ char smem[];
    float* npart = (float*)(smem + NPART_OFF);
    unsigned sb = smem_u32(smem);

    int t = threadIdx.x, wid = t >> 5, lane = t & 31;
    int g = lane >> 2;
    int bid = blockIdx.x;

    /* ---- B fragment table: entry (kk 0..3, nb 0..3) x 32 lanes, uint2.
       b0 bytes j: B[k0+j][bcol], b1: k0+16+j; k0 = 32*kk + 4*qt, bcol = 8*nb+g ---- */
    for (int e = t; e < 512; e += 256) {
        int le = e & 31, nb = (e >> 5) & 3, kk = e >> 7;
        int ge = le >> 2, te = le & 3;
        const float* bp = g_batch + (8 * nb + ge) * D + 32 * kk + 4 * te;
        unsigned l0 = cvte4m3x2(bp[1], bp[0]);
        unsigned l1 = cvte4m3x2(bp[3], bp[2]);
        unsigned h0 = cvte4m3x2(bp[17], bp[16]);
        unsigned h1 = cvte4m3x2(bp[19], bp[18]);
        uint2 w2;
        w2.x = l0 | (l1 << 16);
        w2.y = h0 | (h1 << 16);
        *(uint2*)(smem + BT_OFF + (size_t)((kk * 4 + nb) * 32 + le) * 8) = w2;
    }

    convert_tile(reps, bid * TILE_N, smem, 0, wid, lane, npart);
    __syncthreads();

    int qt = lane & 3;
    unsigned rowa = (unsigned)(wid * 16 + g);
    unsigned gx4 = ((unsigned)g) << 2;

    float tk[8][4]; int tn[8][4];
#pragma unroll
    for (int li = 0; li < 8; li++)
#pragma unroll
        for (int j = 0; j < 4; j++) { tk[li][j] = 3.0e38f; tn[li][j] = 0; }

    int cur = 0;
    for (int tile = bid; tile < NTILES; tile += GRID_MAIN) {
        int tb = tile * TILE_N;

        float acc[4][4];
#pragma unroll
        for (int nb = 0; nb < 4; nb++)
#pragma unroll
            for (int q = 0; q < 4; q++) acc[nb][q] = 0.f;

        const char* abase = smem + ABUF(cur) + rowa * 128;
        const char* btab = smem + BT_OFF + lane * 8;
#pragma unroll
        for (int kk = 0; kk < 4; kk++) {
            unsigned c0 = (unsigned)(8 * kk + qt);
            unsigned sw0 = ((c0 ^ gx4) << 2);
            unsigned sw2 = (((c0 + 4) ^ gx4) << 2);
            unsigned a0 = *(const unsigned*)(abase + sw0);
            unsigned a1 = *(const unsigned*)(abase + 1024 + sw0);   /* +8 rows */
            unsigned a2 = *(const unsigned*)(abase + sw2);
            unsigned a3 = *(const unsigned*)(abase + 1024 + sw2);
#pragma unroll
            for (int nb = 0; nb < 4; nb++) {
                uint2 B0 = *(const uint2*)(btab + (size_t)(kk * 4 + nb) * 256);
                mma16832fp8(acc[nb], a0, a1, a2, a3, B0.x, B0.y);
            }
        }

        /* keys + insert; C fragment map identical to m16n8k16.f32 (verified R9-R14):
           c0/c1: row g cols 2qt,2qt+1 ; c2/c3: row g+8 */
        float nn0 = npart[cur * 128 + wid * 16 + g];
        float nn1 = npart[cur * 128 + wid * 16 + g + 8];
        int r0 = tb + wid * 16 + g;
#pragma unroll
        for (int nb = 0; nb < 4; nb++) {
#pragma unroll
            for (int s = 0; s < 2; s++) {
                int li = nb * 2 + s;
                float k0v = nn0 - 2.0f * acc[nb][s];
                float k1v = nn1 - 2.0f * acc[nb][2 + s];
#pragma unroll
                for (int which = 0; which < 2; which++) {
                    float kv = which ? k1v : k0v;
                    int   iv = which ? (r0 + 8) : r0;
                    if (kv < tk[li][3]) {
                        tk[li][3] = kv; tn[li][3] = iv;
#pragma unroll
                        for (int m = 3; m > 0; m--) {
                            if (tk[li][m] < tk[li][m - 1]) {
                                float fk = tk[li][m]; tk[li][m] = tk[li][m - 1]; tk[li][m - 1] = fk;
                                int ii = tn[li][m]; tn[li][m] = tn[li][m - 1]; tn[li][m - 1] = ii;
                            }
                        }
                    }
                }
            }
        }

        int next = tile + GRID_MAIN;
        if (next < NTILES)
            convert_tile(reps, next * TILE_N, smem, cur ^ 1, wid, lane, npart);
        __syncthreads();
        cur ^= 1;
    }

    /* ---- merge: dump [8][4] lists, thread b<32 scans its 64 lists (verified R12/R14) ---- */
    float* mk = (float*)smem;              /* 32KB */
    int*   mi = (int*)(smem + 32768);      /* 32KB */
#pragma unroll
    for (int li = 0; li < 8; li++)
#pragma unroll
        for (int j = 0; j < 4; j++) {
            mk[(t * 8 + li) * 4 + j] = tk[li][j];
            mi[(t * 8 + li) * 4 + j] = tn[li][j];
        }
    __syncthreads();

    if (t < 32) {
        int b = t;
        int li = (b >> 3) * 2 + (b & 1);
        int qb = (b >> 1) & 3;
        float fk[5]; int fn[5];
#pragma unroll
        for (int j = 0; j < 5; j++) { fk[j] = 3.0e38f; fn[j] = 0; }
        for (int m = 0; m < 64; m++) {
            int tt = qb + 4 * m;
            int base = (tt * 8 + li) * 4;
#pragma unroll
            for (int j = 0; j < 4; j++) {
                float kv = mk[base + j];
                if (kv < fk[4]) {
                    int iv = mi[base + j];
                    fk[4] = kv; fn[4] = iv;
#pragma unroll
                    for (int m2 = 4; m2 > 0; m2--) {
                        if (fk[m2] < fk[m2 - 1]) {
                            float a2 = fk[m2]; fk[m2] = fk[m2 - 1]; fk[m2 - 1] = a2;
                            int i2 = fn[m2]; fn[m2] = fn[m2 - 1]; fn[m2 - 1] = i2;
                        }
                    }
                } else break;
            }
        }
        int basec = (b * GRID_MAIN + bid) * KSEL;
#pragma unroll
        for (int j = 0; j < 5; j++) { g_ckey[basec + j] = fk[j]; g_cidx[basec + j] = fn[j]; }
    }
}

/* ================= final: depth-5 merge -> 40 cands -> exact rescore -> softmax ================= */
__global__ void __launch_bounds__(256) final_kernel(const float* __restrict__ actions,
                                                    const float* __restrict__ reps,
                                                    float* __restrict__ out) {
    __shared__ float wk[NCAND];
    __shared__ int   wi[NCAND];
    __shared__ float exk[NCAND];
    int b = blockIdx.x, t = threadIdx.x;
    int w = t >> 5, lane = t & 31;

    const int total = GRID_MAIN * KSEL;
    const float* ck = g_ckey + b * total;
    const int*   ci = g_cidx + b * total;

    float tk[5]; int tn[5];
#pragma unroll
    for (int j = 0; j < 5; j++) { tk[j] = 3.0e38f; tn[j] = 0; }
    for (int i = t; i < total; i += 256) {
        float key = ck[i];
        if (key < tk[4]) {
            int idx = ci[i];
            tk[4] = key; tn[4] = idx;
#pragma unroll
            for (int j = 4; j > 0; j--) {
                if (tk[j] < tk[j - 1]) {
                    float fk = tk[j]; tk[j] = tk[j - 1]; tk[j - 1] = fk;
                    int ii = tn[j]; tn[j] = tn[j - 1]; tn[j - 1] = ii;
                }
            }
        }
    }

#pragma unroll
    for (int o = 16; o > 0; o >>= 1) {
        float ok[5]; int on[5];
#pragma unroll
        for (int j = 0; j < 5; j++) {
            ok[j] = __shfl_xor_sync(0xffffffffu, tk[j], o);
            on[j] = __shfl_xor_sync(0xffffffffu, tn[j], o);
        }
#pragma unroll
        for (int j = 0; j < 5; j++) {
            float key = ok[j]; int idx = on[j];
            if (key < tk[4]) {
                tk[4] = key; tn[4] = idx;
#pragma unroll
                for (int m = 4; m > 0; m--) {
                    if (tk[m] < tk[m - 1]) {
                        float fk = tk[m]; tk[m] = tk[m - 1]; tk[m - 1] = fk;
                        int ii = tn[m]; tn[m] = tn[m - 1]; tn[m - 1] = ii;
                    }
                }
            }
        }
    }
    if (lane == 0) {
#pragma unroll
        for (int j = 0; j < 5; j++) { wk[w * KSEL + j] = tk[j]; wi[w * KSEL + j] = tn[j]; }
    }
    __syncthreads();

    /* exact fp32 rescore; warp w does candidates w*5..w*5+4 */
    {
        float4 av = ((const float4*)(g_batch + b * D))[lane];
#pragma unroll
        for (int cc = 0; cc < 5; cc++) {
            int c = w * 5 + cc;
            int idx = wi[c];
            float4 rv = ((const float4*)(reps + (size_t)idx * D))[lane];
            float dot = fmaf(av.x, rv.x, fmaf(av.y, rv.y, fmaf(av.z, rv.z, av.w * rv.w)));
            float rn  = fmaf(rv.x, rv.x, fmaf(rv.y, rv.y, fmaf(rv.z, rv.z, rv.w * rv.w)));
#pragma unroll
            for (int o = 16; o > 0; o >>= 1) {
                dot += __shfl_xor_sync(0xffffffffu, dot, o);
                rn  += __shfl_xor_sync(0xffffffffu, rn, o);
            }
            if (lane == 0) exk[c] = rn - 2.0f * dot;
        }
    }
    __syncthreads();

    if (t == 0) {
        float fk[5]; int fn[5];
#pragma unroll
        for (int j = 0; j < 5; j++) { fk[j] = 3.0e38f; fn[j] = 0; }
#pragma unroll
        for (int c = 0; c < NCAND; c++) {
            float kv = exk[c];
            if (kv < fk[4]) {
                int iv = wi[c];
                fk[4] = kv; fn[4] = iv;
#pragma unroll
                for (int m = 4; m > 0; m--) {
                    if (fk[m] < fk[m - 1]) {
                        float a2 = fk[m]; fk[m] = fk[m - 1]; fk[m - 1] = a2;
                        int i2 = fn[m]; fn[m] = fn[m - 1]; fn[m - 1] = i2;
                    }
                }
            }
        }
        float an = g_anorm[b];
        float dloc[KSEL];
        float dmin = 3.0e38f;
#pragma unroll
        for (int j = 0; j < KSEL; j++) {
            dloc[j] = sqrtf(fmaxf(an + fk[j], 1e-12f));
            dmin = fminf(dmin, dloc[j]);
        }
        float wsum = 0.f;
        float pred[ADIM];
#pragma unroll
        for (int a = 0; a < ADIM; a++) pred[a] = 0.f;
#pragma unroll
        for (int j = 0; j < KSEL; j++) {
            float wgt = expf(-(dloc[j] - dmin));
            wsum += wgt;
            const float* arow = actions + (size_t)fn[j] * ADIM;
#pragma unroll
            for (int a = 0; a < ADIM; a++) pred[a] = fmaf(wgt, arow[a], pred[a]);
        }
        float inv = 1.0f / wsum;
#pragma unroll
        for (int a = 0; a < ADIM; a++) out[b * ADIM + a] = pred[a] * inv;
    }
}

/* ================= launch ================= */
extern "C" void kernel_launch(void* const* d_in, const int* in_sizes, int n_in,
                              void* d_out, int out_size) {
    (void)in_sizes; (void)n_in; (void)out_size;
    const float* x       = (const float*)d_in[0];
    const float* W       = (const float*)d_in[1];
    const float* bias    = (const float*)d_in[2];
    const float* reps    = (const float*)d_in[3];
    const float* actions = (const float*)d_in[4];
    float* out = (float*)d_out;

    cudaFuncSetAttribute(dist_kernel, cudaFuncAttributeMaxDynamicSharedMemorySize, SMEM_TOTAL);

    enc_partial<<<dim3(B, ENC_CHUNKS), 128>>>(x, W);
    enc_reduce<<<B, 128>>>(bias);
    dist_kernel<<<GRID_MAIN, 256, SMEM_TOTAL>>>(reps);
    final_kernel<<<B, 256>>>(actions, reps, out);
}

// round 17
// speedup vs baseline: 1.4056x; 1.0144x over previous
#include <cuda_runtime.h>
#include <math.h>
#include <stdint.h>

#define B 32
#define DIN 2048
#define D 128
#define NREPS 400000
#define ADIM 7
#define KSEL 5
#define NCAND 40                  /* 8 warps x depth-5 lists -> exact rescore */

#define GRID_MAIN 296
#define TILE_N 128
#define NTILES (NREPS / TILE_N)   /* 3125, exact */
#define ENC_CHUNKS 16

/* smem layout (bytes) */
#define STAGE_OFF   0                 /* fp32 staging of one tile: 128 rows x 512B = 64KB */
#define PLANE_OFF   65536             /* fp8 plane: 128 rows x 128B, swizzled = 16KB */
#define BT_OFF      81920             /* B frag table: 4KB */
#define NPART_OFF   86016             /* 128 floats */
#define SMEM_TOTAL  86528

/* ---------------- device scratch ---------------- */
__device__ float g_enc_part[ENC_CHUNKS][B][D];
__device__ float g_batch[B * D];
__device__ float g_anorm[B];
__device__ float g_ckey[B * GRID_MAIN * KSEL];
__device__ int   g_cidx[B * GRID_MAIN * KSEL];

/* ---------------- helpers ---------------- */
__device__ __forceinline__ unsigned short cvte4m3x2(float hi, float lo) {
    unsigned short r;
    asm("cvt.rn.satfinite.e4m3x2.f32 %0, %1, %2;" : "=h"(r) : "f"(hi), "f"(lo));
    return r;
}
__device__ __forceinline__ void mma16832fp8(float* c, unsigned a0, unsigned a1,
                                            unsigned a2, unsigned a3,
                                            unsigned b0, unsigned b1) {
    asm volatile(
        "mma.sync.aligned.m16n8k32.row.col.f32.e4m3.e4m3.f32 "
        "{%0,%1,%2,%3}, {%4,%5,%6,%7}, {%8,%9}, {%0,%1,%2,%3};"
        : "+f"(c[0]), "+f"(c[1]), "+f"(c[2]), "+f"(c[3])
        : "r"(a0), "r"(a1), "r"(a2), "r"(a3), "r"(b0), "r"(b1));
}
__device__ __forceinline__ unsigned smem_u32(const void* p) {
    unsigned a;
    asm("{ .reg .u64 t; cvta.to.shared.u64 t, %1; cvt.u32.u64 %0, t; }" : "=r"(a) : "l"(p));
    return a;
}
__device__ __forceinline__ void cp_async16(unsigned dst, const void* src) {
    asm volatile("cp.async.cg.shared.global [%0], [%1], 16;" :: "r"(dst), "l"(src));
}
__device__ __forceinline__ void cp_commit() {
    asm volatile("cp.async.commit_group;" ::: "memory");
}
__device__ __forceinline__ void cp_wait0() {
    asm volatile("cp.async.wait_group 0;" ::: "memory");
}

/* ================= encoder split-K partial ================= */
__global__ void enc_partial(const float* __restrict__ x,
                            const float* __restrict__ W) {
    __shared__ float xs[128];
    int b = blockIdx.x, c = blockIdx.y, t = threadIdx.x;
    xs[t] = x[b * DIN + c * 128 + t];
    __syncthreads();
    const float* Wp = W + (c * 128) * D + t;
    float a0 = 0.f, a1 = 0.f, a2 = 0.f, a3 = 0.f;
#pragma unroll
    for (int k = 0; k < 128; k += 4) {
        a0 = fmaf(xs[k + 0], Wp[(k + 0) * D], a0);
        a1 = fmaf(xs[k + 1], Wp[(k + 1) * D], a1);
        a2 = fmaf(xs[k + 2], Wp[(k + 2) * D], a2);
        a3 = fmaf(xs[k + 3], Wp[(k + 3) * D], a3);
    }
    g_enc_part[c][b][t] = (a0 + a1) + (a2 + a3);
}

/* ================= encoder reduce + norms ================= */
__global__ void enc_reduce(const float* __restrict__ bias) {
    __shared__ float red[4];
    int b = blockIdx.x, t = threadIdx.x;
    float s = bias[t];
#pragma unroll
    for (int c = 0; c < ENC_CHUNKS; c++) s += g_enc_part[c][b][t];
    g_batch[b * D + t] = s;
    float sq = s * s;
#pragma unroll
    for (int o = 16; o > 0; o >>= 1) sq += __shfl_down_sync(0xffffffffu, sq, o);
    if ((t & 31) == 0) red[t >> 5] = sq;
    __syncthreads();
    if (t == 0) g_anorm[b] = red[0] + red[1] + red[2] + red[3];
}

/* ---- convert from smem stage: thread (wid,lane): rows wid*16..+15, dims 4l..4l+3 ---- */
__device__ __forceinline__ void convert_stage(char* smem, int wid, int lane, float* npart) {
#pragma unroll
    for (int i = 0; i < 16; i++) {
        int r = wid * 16 + i;
        float4 v = *(const float4*)(smem + STAGE_OFF + (size_t)r * 512 + lane * 16);
        unsigned lo = cvte4m3x2(v.y, v.x);
        unsigned hi = cvte4m3x2(v.w, v.z);
        unsigned word = lo | (hi << 16);
        float na = fmaf(v.x, v.x, fmaf(v.y, v.y, fmaf(v.z, v.z, v.w * v.w)));
#pragma unroll
        for (int o = 16; o > 0; o >>= 1) na += __shfl_xor_sync(0xffffffffu, na, o);
        if (lane == 0) npart[r] = na;
        unsigned off = (unsigned)PLANE_OFF + (unsigned)r * 128u
                     + (((unsigned)lane ^ (((unsigned)(r & 7)) << 2)) << 2);
        *(unsigned*)(smem + off) = word;
    }
}

/* ================= main distance kernel: fp8 m16n8k32, cp.async staged ================= */
__global__ void __launch_bounds__(256, 2) dist_kernel(const float* __restrict__ reps) {
    extern __shared__ char smem[];
    float* npart = (float*)(smem + NPART_OFF);
    unsigned sb = smem_u32(smem);

    int t = threadIdx.x, wid = t >> 5, lane = t & 31;
    int g = lane >> 2;
    int bid = blockIdx.x;

    /* ---- prologue: stage tile bid ---- */
    {
        const char* gsrc = (const char*)reps + (size_t)bid * TILE_N * 512;
#pragma unroll
        for (int j = 0; j < 16; j++) {
            int chunk = t + 256 * j;
            cp_async16(sb + STAGE_OFF + chunk * 16, gsrc + (size_t)chunk * 16);
        }
        cp_commit();
    }

    /* ---- B fragment table (layout verified R16) ---- */
    for (int e = t; e < 512; e += 256) {
        int le = e & 31, nb = (e >> 5) & 3, kk = e >> 7;
        int ge = le >> 2, te = le & 3;
        const float* bp = g_batch + (8 * nb + ge) * D + 32 * kk + 4 * te;
        unsigned l0 = cvte4m3x2(bp[1], bp[0]);
        unsigned l1 = cvte4m3x2(bp[3], bp[2]);
        unsigned h0 = cvte4m3x2(bp[17], bp[16]);
        unsigned h1 = cvte4m3x2(bp[19], bp[18]);
        uint2 w2;
        w2.x = l0 | (l1 << 16);
        w2.y = h0 | (h1 << 16);
        *(uint2*)(smem + BT_OFF + (size_t)((kk * 4 + nb) * 32 + le) * 8) = w2;
    }

    int qt = lane & 3;
    unsigned rowa = (unsigned)(wid * 16 + g);
    unsigned gx4 = ((unsigned)g) << 2;

    float tk[8][4]; int tn[8][4];
#pragma unroll
    for (int li = 0; li < 8; li++)
#pragma unroll
        for (int j = 0; j < 4; j++) { tk[li][j] = 3.0e38f; tn[li][j] = 0; }

    cp_wait0();
    __syncthreads();   /* stage(tile bid) complete for all threads; BT ready */

    for (int tile = bid; tile < NTILES; tile += GRID_MAIN) {
        int tb = tile * TILE_N;

        /* ---- convert stage -> fp8 plane + norms ---- */
        convert_stage(smem, wid, lane, npart);
        __syncthreads();   /* plane + npart ready; stage free to overwrite */

        /* ---- issue prefetch of next tile into stage (lands during MMA) ---- */
        int next = tile + GRID_MAIN;
        if (next < NTILES) {
            const char* gsrc = (const char*)reps + (size_t)next * TILE_N * 512;
#pragma unroll
            for (int j = 0; j < 16; j++) {
                int chunk = t + 256 * j;
                cp_async16(sb + STAGE_OFF + chunk * 16, gsrc + (size_t)chunk * 16);
            }
        }
        cp_commit();

        /* ---- MMA phase (verified R16) ---- */
        float acc[4][4];
#pragma unroll
        for (int nb = 0; nb < 4; nb++)
#pragma unroll
            for (int q = 0; q < 4; q++) acc[nb][q] = 0.f;

        const char* abase = smem + PLANE_OFF + rowa * 128;
        const char* btab = smem + BT_OFF + lane * 8;
#pragma unroll
        for (int kk = 0; kk < 4; kk++) {
            unsigned c0 = (unsigned)(8 * kk + qt);
            unsigned sw0 = ((c0 ^ gx4) << 2);
            unsigned sw2 = (((c0 + 4) ^ gx4) << 2);
            unsigned a0 = *(const unsigned*)(abase + sw0);
            unsigned a1 = *(const unsigned*)(abase + 1024 + sw0);
            unsigned a2 = *(const unsigned*)(abase + sw2);
            unsigned a3 = *(const unsigned*)(abase + 1024 + sw2);
#pragma unroll
            for (int nb = 0; nb < 4; nb++) {
                uint2 B0 = *(const uint2*)(btab + (size_t)(kk * 4 + nb) * 256);
                mma16832fp8(acc[nb], a0, a1, a2, a3, B0.x, B0.y);
            }
        }

        /* ---- keys + insert (verified R16) ---- */
        float nn0 = npart[wid * 16 + g];
        float nn1 = npart[wid * 16 + g + 8];
        int r0 = tb + wid * 16 + g;
#pragma unroll
        for (int nb = 0; nb < 4; nb++) {
#pragma unroll
            for (int s = 0; s < 2; s++) {
                int li = nb * 2 + s;
                float k0v = nn0 - 2.0f * acc[nb][s];
                float k1v = nn1 - 2.0f * acc[nb][2 + s];
#pragma unroll
                for (int which = 0; which < 2; which++) {
                    float kv = which ? k1v : k0v;
                    int   iv = which ? (r0 + 8) : r0;
                    if (kv < tk[li][3]) {
                        tk[li][3] = kv; tn[li][3] = iv;
#pragma unroll
                        for (int m = 3; m > 0; m--) {
                            if (tk[li][m] < tk[li][m - 1]) {
                                float fk = tk[li][m]; tk[li][m] = tk[li][m - 1]; tk[li][m - 1] = fk;
                                int ii = tn[li][m]; tn[li][m] = tn[li][m - 1]; tn[li][m - 1] = ii;
                            }
                        }
                    }
                }
            }
        }

        cp_wait0();        /* own async copies done */
        __syncthreads();   /* all threads' copies done; plane/npart reads done */
    }

    /* ---- merge: dump [8][4] lists, thread b<32 scans its 64 lists (verified R12-R16) ---- */
    float* mk = (float*)smem;              /* 32KB (stage region, free now) */
    int*   mi = (int*)(smem + 32768);      /* 32KB */
#pragma unroll
    for (int li = 0; li < 8; li++)
#pragma unroll
        for (int j = 0; j < 4; j++) {
            mk[(t * 8 + li) * 4 + j] = tk[li][j];
            mi[(t * 8 + li) * 4 + j] = tn[li][j];
        }
    __syncthreads();

    if (t < 32) {
        int b = t;
        int li = (b >> 3) * 2 + (b & 1);
        int qb = (b >> 1) & 3;
        float fk[5]; int fn[5];
#pragma unroll
        for (int j = 0; j < 5; j++) { fk[j] = 3.0e38f; fn[j] = 0; }
        for (int m = 0; m < 64; m++) {
            int tt = qb + 4 * m;
            int base = (tt * 8 + li) * 4;
#pragma unroll
            for (int j = 0; j < 4; j++) {
                float kv = mk[base + j];
                if (kv < fk[4]) {
                    int iv = mi[base + j];
                    fk[4] = kv; fn[4] = iv;
#pragma unroll
                    for (int m2 = 4; m2 > 0; m2--) {
                        if (fk[m2] < fk[m2 - 1]) {
                            float a2 = fk[m2]; fk[m2] = fk[m2 - 1]; fk[m2 - 1] = a2;
                            int i2 = fn[m2]; fn[m2] = fn[m2 - 1]; fn[m2 - 1] = i2;
                        }
                    }
                } else break;
            }
        }
        int basec = (b * GRID_MAIN + bid) * KSEL;
#pragma unroll
        for (int j = 0; j < 5; j++) { g_ckey[basec + j] = fk[j]; g_cidx[basec + j] = fn[j]; }
    }
}

/* ================= final: depth-5 merge -> 40 cands -> exact rescore -> softmax ================= */
__global__ void __launch_bounds__(256) final_kernel(const float* __restrict__ actions,
                                                    const float* __restrict__ reps,
                                                    float* __restrict__ out) {
    __shared__ float wk[NCAND];
    __shared__ int   wi[NCAND];
    __shared__ float exk[NCAND];
    int b = blockIdx.x, t = threadIdx.x;
    int w = t >> 5, lane = t & 31;

    const int total = GRID_MAIN * KSEL;
    const float* ck = g_ckey + b * total;
    const int*   ci = g_cidx + b * total;

    float tk[5]; int tn[5];
#pragma unroll
    for (int j = 0; j < 5; j++) { tk[j] = 3.0e38f; tn[j] = 0; }
    for (int i = t; i < total; i += 256) {
        float key = ck[i];
        if (key < tk[4]) {
            int idx = ci[i];
            tk[4] = key; tn[4] = idx;
#pragma unroll
            for (int j = 4; j > 0; j--) {
                if (tk[j] < tk[j - 1]) {
                    float fk = tk[j]; tk[j] = tk[j - 1]; tk[j - 1] = fk;
                    int ii = tn[j]; tn[j] = tn[j - 1]; tn[j - 1] = ii;
                }
            }
        }
    }

#pragma unroll
    for (int o = 16; o > 0; o >>= 1) {
        float ok[5]; int on[5];
#pragma unroll
        for (int j = 0; j < 5; j++) {
            ok[j] = __shfl_xor_sync(0xffffffffu, tk[j], o);
            on[j] = __shfl_xor_sync(0xffffffffu, tn[j], o);
        }
#pragma unroll
        for (int j = 0; j < 5; j++) {
            float key = ok[j]; int idx = on[j];
            if (key < tk[4]) {
                tk[4] = key; tn[4] = idx;
#pragma unroll
                for (int m = 4; m > 0; m--) {
                    if (tk[m] < tk[m - 1]) {
                        float fk = tk[m]; tk[m] = tk[m - 1]; tk[m - 1] = fk;
                        int ii = tn[m]; tn[m] = tn[m - 1]; tn[m - 1] = ii;
                    }
                }
            }
        }
    }
    if (lane == 0) {
#pragma unroll
        for (int j = 0; j < 5; j++) { wk[w * KSEL + j] = tk[j]; wi[w * KSEL + j] = tn[j]; }
    }
    __syncthreads();

    {
        float4 av = ((const float4*)(g_batch + b * D))[lane];
#pragma unroll
        for (int cc = 0; cc < 5; cc++) {
            int c = w * 5 + cc;
            int idx = wi[c];
            float4 rv = ((const float4*)(reps + (size_t)idx * D))[lane];
            float dot = fmaf(av.x, rv.x, fmaf(av.y, rv.y, fmaf(av.z, rv.z, av.w * rv.w)));
            float rn  = fmaf(rv.x, rv.x, fmaf(rv.y, rv.y, fmaf(rv.z, rv.z, rv.w * rv.w)));
#pragma unroll
            for (int o = 16; o > 0; o >>= 1) {
                dot += __shfl_xor_sync(0xffffffffu, dot, o);
                rn  += __shfl_xor_sync(0xffffffffu, rn, o);
            }
            if (lane == 0) exk[c] = rn - 2.0f * dot;
        }
    }
    __syncthreads();

    if (t == 0) {
        float fk[5]; int fn[5];
#pragma unroll
        for (int j = 0; j < 5; j++) { fk[j] = 3.0e38f; fn[j] = 0; }
#pragma unroll
        for (int c = 0; c < NCAND; c++) {
            float kv = exk[c];
            if (kv < fk[4]) {
                int iv = wi[c];
                fk[4] = kv; fn[4] = iv;
#pragma unroll
                for (int m = 4; m > 0; m--) {
                    if (fk[m] < fk[m - 1]) {
                        float a2 = fk[m]; fk[m] = fk[m - 1]; fk[m - 1] = a2;
                        int i2 = fn[m]; fn[m] = fn[m - 1]; fn[m - 1] = i2;
                    }
                }
            }
        }
        float an = g_anorm[b];
        float dloc[KSEL];
        float dmin = 3.0e38f;
#pragma unroll
        for (int j = 0; j < KSEL; j++) {
            dloc[j] = sqrtf(fmaxf(an + fk[j], 1e-12f));
            dmin = fminf(dmin, dloc[j]);
        }
        float wsum = 0.f;
        float pred[ADIM];
#pragma unroll
        for (int a = 0; a < ADIM; a++) pred[a] = 0.f;
#pragma unroll
        for (int j = 0; j < KSEL; j++) {
            float wgt = expf(-(dloc[j] - dmin));
            wsum += wgt;
            const float* arow = actions + (size_t)fn[j] * ADIM;
#pragma unroll
            for (int a = 0; a < ADIM; a++) pred[a] = fmaf(wgt, arow[a], pred[a]);
        }
        float inv = 1.0f / wsum;
#pragma unroll
        for (int a = 0; a < ADIM; a++) out[b * ADIM + a] = pred[a] * inv;
    }
}

/* ================= launch ================= */
extern "C" void kernel_launch(void* const* d_in, const int* in_sizes, int n_in,
                              void* d_out, int out_size) {
    (void)in_sizes; (void)n_in; (void)out_size;
    const float* x       = (const float*)d_in[0];
    const float* W       = (const float*)d_in[1];
    const float* bias    = (const float*)d_in[2];
    const float* reps    = (const float*)d_in[3];
    const float* actions = (const float*)d_in[4];
    float* out = (float*)d_out;

    cudaFuncSetAttribute(dist_kernel, cudaFuncAttributeMaxDynamicSharedMemorySize, SMEM_TOTAL);

    enc_partial<<<dim3(B, ENC_CHUNKS), 128>>>(x, W);
    enc_reduce<<<B, 128>>>(bias);
    dist_kernel<<<GRID_MAIN, 256, SMEM_TOTAL>>>(reps);
    final_kernel<<<B, 256>>>(actions, reps, out);
}